// round 10
// baseline (speedup 1.0000x reference)
#include <cuda_runtime.h>
#include <stdint.h>
#include <math.h>

// ---------------------------------------------------------------------------
// ProposalLayer: decode -> clip -> min-size filter -> top-12000 -> NMS(0.7)
//                -> first 2000 kept boxes (zero padded)
// R9: single persistent mega-kernel (148 blocks, software grid barriers)
//     + column-major NMS mask with incremental suppression bitmap.
// ---------------------------------------------------------------------------

#define NMAX    147456
#define NPRE    12000
#define NPOST   2000
#define CAP     16384
#define NMS_T   0.7f
#define WPR     188          // u64 words per 12032-row bitmap
#define TOPPAD  12032        // 188*64
#define B1      4096         // stage-1 NMS coverage (64 chunks)
#define NBLK    148
#define NTHR    256
#define GSZ     (NBLK * NTHR)
#define NTILES1 2080                       // 64*65/2
#define NTILESA ((WPR * (WPR + 1)) / 2)    // 17766

// ------------------------- scratch (device globals) ------------------------
__device__ unsigned int       g_keys[NMAX];
__device__ float4             g_boxes[NMAX];
__device__ int                g_hist1[65536];
__device__ int                g_hist2[65536];
__device__ unsigned int       g_T;
__device__ int                g_C1;
__device__ int                g_need2;
__device__ unsigned int       g_kthKey;
__device__ int                g_candCount;
__device__ unsigned long long g_cand[CAP];
__device__ int                g_rank[CAP];
__device__ float4             g_topBox[TOPPAD];
__device__ float              g_topArea[TOPPAD];
__device__ int                g_validTop;
__device__ unsigned long long g_maskT[(size_t)TOPPAD * WPR];  // column-major
__device__ unsigned long long g_diag[TOPPAD];
__device__ int                g_kept;
__device__ int                g_needMore;
__device__ unsigned long long g_keptMaskG[WPR];
__device__ unsigned long long g_supBG[WPR];
__device__ int                g_barCount;

// --------------------------- software grid barrier -------------------------
__device__ __forceinline__ void gbar(int target) {
    __syncthreads();
    if (threadIdx.x == 0) {
        __threadfence();
        atomicAdd(&g_barCount, 1);
        while (__ldcg((const int*)&g_barCount) < target) __nanosleep(128);
        __threadfence();
    }
    __syncthreads();
}

// ------------------------------- init kernel -------------------------------
__global__ void k_init(float* __restrict__ out) {
    int gid = blockIdx.x * blockDim.x + threadIdx.x;
    for (int k = gid; k < 65536; k += GSZ) { g_hist1[k] = 0; g_hist2[k] = 0; }
    for (int k = gid; k < NPOST * 4; k += GSZ) out[k] = 0.0f;
    for (int k = gid; k < CAP; k += GSZ) g_rank[k] = 0;
    if (gid == 0) {
        g_candCount = 0;
        g_need2     = 0;
        g_T         = 0;
        g_C1        = 0;
        g_kthKey    = 1u;     // fallback: gather all valid
        g_needMore  = 0;
        g_kept      = 0;
        g_validTop  = 0;
        g_barCount  = 0;
    }
}

// --------------------------- IoU (reference-exact) -------------------------
__device__ __forceinline__ bool iou_gt(float4 a, float aa, float4 b, float ab) {
    float ty = fmaxf(a.x, b.x);
    float tx = fmaxf(a.y, b.y);
    float by = fminf(a.z, b.z);
    float bx = fminf(a.w, b.w);
    float hh = fmaxf(__fsub_rn(by, ty), 0.0f);
    float ww = fmaxf(__fsub_rn(bx, tx), 0.0f);
    float inter = __fmul_rn(hh, ww);
    float uni = __fsub_rn(__fadd_rn(aa, ab), inter);
    float iou = __fdiv_rn(inter, fmaxf(uni, 1e-9f));
    return iou > NMS_T;
}

// ------------------ two-level parallel threshold search --------------------
// block0 only. mode 0: level-1 (sets g_T/g_C1 and g_kthKey or g_need2).
// mode 1: level-2 refinement (sets exact g_kthKey).
__device__ void findPhase(const int* __restrict__ hist, int baseCount, int mode) {
    __shared__ int sc1[NTHR];
    __shared__ int sTc, sBase;
    int t = threadIdx.x;
    if (t == 0) sTc = -1;
    const int4* h4 = (const int4*)hist;
    int s = 0;
#pragma unroll 16
    for (int k = 0; k < 64; k++) {
        int4 v = __ldcg(h4 + t * 64 + k);
        s += v.x + v.y + v.z + v.w;
    }
    sc1[t] = s;
    __syncthreads();
    int s0 = s;
    for (int o = 1; o < NTHR; o <<= 1) {   // inclusive suffix sum
        int v = sc1[t] + ((t + o < NTHR) ? sc1[t + o] : 0);
        __syncthreads();
        sc1[t] = v;
        __syncthreads();
    }
    int Sincl = sc1[t];
    int Sexcl = Sincl - s0;
    if (baseCount + Sexcl < NPRE && baseCount + Sincl >= NPRE) {
        sTc = t; sBase = baseCount + Sexcl;
    }
    __syncthreads();
    int tc = sTc;
    if (tc < 0) return;   // fewer than NPRE total: keep fallback kthKey

    int b = tc * NTHR + t;
    int h = __ldcg(&hist[b]);
    sc1[t] = h;
    __syncthreads();
    for (int o = 1; o < NTHR; o <<= 1) {
        int v = sc1[t] + ((t + o < NTHR) ? sc1[t + o] : 0);
        __syncthreads();
        sc1[t] = v;
        __syncthreads();
    }
    int cum = sBase + sc1[t];     // count of keys in bins >= b at this level
    int cumNext = cum - h;        // count in bins > b
    if (cumNext < NPRE && cum >= NPRE) {
        if (mode == 0) {
            g_T = (unsigned)(b);
            g_C1 = cumNext;
            if (cum <= CAP) {
                unsigned kk = ((unsigned)b) << 16;
                g_kthKey = kk ? kk : 1u;
            } else {
                g_need2 = 1;
            }
        } else {
            g_kthKey = (g_T << 16) | (unsigned)b;
        }
    }
    __syncthreads();
}

// -------- triangular tile index -> (row-block, col-block), cb <= rb --------
__device__ __forceinline__ int2 triRC(int idx) {
    int r = (int)((sqrtf(8.0f * (float)idx + 1.0f) - 1.0f) * 0.5f);
    while ((r + 1) * (r + 2) / 2 <= idx) ++r;
    while (r * (r + 1) / 2 > idx) --r;
    return make_int2(r, idx - r * (r + 1) / 2);
}

// ---- mask phase: column-major suppression words + diagonal row words ------
__device__ void maskPhase(int tileBeg, int tileEnd) {
    __shared__ float4 rB[64];
    __shared__ float  rA[64];
    __shared__ float4 cBx[64];
    __shared__ float  cAx[64];
    __shared__ unsigned long long mP[4][64];
    int tid = threadIdx.x;
    int a = tid & 63, q = tid >> 6;

    for (int idx = tileBeg + blockIdx.x; idx < tileEnd; idx += NBLK) {
        int2 rc = triRC(idx);
        int rb = rc.x, cb = rc.y;
        if (tid < 64) { cBx[tid] = g_topBox[cb * 64 + tid]; cAx[tid] = g_topArea[cb * 64 + tid]; }
        else if (tid < 128) { int r = tid - 64; rB[r] = g_topBox[rb * 64 + r]; rA[r] = g_topArea[rb * 64 + r]; }
        __syncthreads();

        int rmax = NPRE - rb * 64; if (rmax > 64) rmax = 64;
        bool isDiag = (rb == cb);
        {   // transposed: column j=a, rows r in [q*16, q*16+16)
            float4 cbox = cBx[a];
            float  ca = cAx[a];
            unsigned long long w = 0ull;
            int r0 = q * 16, r1 = r0 + 16; if (r1 > rmax) r1 = rmax;
            for (int r = r0; r < r1; r++) {
                if (isDiag && r <= a) continue;
                if (iou_gt(cbox, ca, rB[r], rA[r])) w |= 1ull << r;
            }
            mP[q][a] = w;
        }
        __syncthreads();
        if (q == 0)
            g_maskT[(size_t)(cb * 64 + a) * WPR + rb] =
                mP[0][a] | mP[1][a] | mP[2][a] | mP[3][a];
        __syncthreads();

        if (isDiag) {   // row-major diag word: row r=a, bits j<r
            float4 rbox = rB[a];
            float  ra = rA[a];
            unsigned long long w = 0ull;
            int j0 = q * 16, j1 = j0 + 16; if (j1 > a) j1 = a;
            for (int j = j0; j < j1; j++)
                if (iou_gt(rbox, ra, cBx[j], cAx[j])) w |= 1ull << j;
            mP[q][a] = w;
            __syncthreads();
            if (q == 0 && a < rmax)
                g_diag[rb * 64 + a] = mP[0][a] | mP[1][a] | mP[2][a] | mP[3][a];
            __syncthreads();
        }
    }
}

// ------- resolve: frontier greedy + incremental suppression bitmap ---------
// block0 only, 256 threads, 8 warps.
__device__ void resolvePhase(int stage, float* __restrict__ out) {
    __shared__ unsigned long long supB[WPR];
    __shared__ unsigned long long keptMask[WPR];
    __shared__ unsigned long long sDiag[2][64];
    __shared__ unsigned long long sK;
    __shared__ int sKept, sStop;
    __shared__ int wordBase[WPR];

    int tid = threadIdx.x, lane = tid & 31, warp = tid >> 5;
    int vt = g_validTop;
    int start = stage ? B1 : 0;
    int end   = stage ? vt : (vt < B1 ? vt : B1);
    int kept0 = stage ? g_kept : 0;

    if (stage) {
        for (int w = tid; w < WPR; w += NTHR) {
            keptMask[w] = g_keptMaskG[w];
            supB[w] = (w < B1 / 64) ? g_supBG[w] : 0ull;
        }
    } else {
        for (int w = tid; w < WPR; w += NTHR) { keptMask[w] = 0ull; supB[w] = 0ull; }
    }
    __syncthreads();

    if (stage) {
        // rebuild supB words >= 64 from stage-1 kept columns (maskT now complete)
        if (tid < WPR - B1 / 64) {
            int w = B1 / 64 + tid;
            unsigned long long acc = 0ull;
            for (int kw = 0; kw < B1 / 64; kw++) {
                unsigned long long km = keptMask[kw];
                while (km) {
                    int jj = __ffsll(km) - 1; km &= km - 1;
                    acc |= __ldg(&g_maskT[(size_t)(kw * 64 + jj) * WPR + w]);
                }
            }
            supB[w] = acc;
        }
        __syncthreads();
    }

    if (tid == 0) { sKept = kept0; sStop = (start >= end || kept0 >= NPOST) ? 1 : 0; }
    if (tid < 64) sDiag[0][tid] = (start + tid < end) ? __ldg(&g_diag[start + tid]) : 0ull;
    __syncthreads();

    if (!sStop) {
        int kept = kept0;
        int pb = 0;
        for (int base = start; ; base += 64, pb ^= 1) {
            int cw = base >> 6;
            int cn = end - base; if (cn > 64) cn = 64;
            int nbase = base + 64;

            if (warp == 0) {
                // exact greedy within chunk: frontier rounds == sequential greedy
                unsigned long long sup = supB[cw];
                unsigned long long cand = ~sup;
                if (cn < 64) cand &= (1ull << cn) - 1ull;
                unsigned long long rowLo = sDiag[pb][lane];
                unsigned long long rowHi = sDiag[pb][lane + 32];
                unsigned long long U = cand, K = 0ull;
                while (U) {
                    bool flo = ((U >> lane) & 1ull) && ((rowLo & U) == 0ull);
                    bool fhi = ((U >> (lane + 32)) & 1ull) && ((rowHi & U) == 0ull);
                    unsigned long long F =
                          (unsigned long long)__ballot_sync(0xffffffffu, flo)
                        | ((unsigned long long)__ballot_sync(0xffffffffu, fhi) << 32);
                    K |= F;
                    bool qlo = (rowLo & F) != 0ull;
                    bool qhi = (rowHi & F) != 0ull;
                    unsigned long long S =
                          (unsigned long long)__ballot_sync(0xffffffffu, qlo)
                        | ((unsigned long long)__ballot_sync(0xffffffffu, qhi) << 32);
                    U &= ~(F | S | K);
                }
                int c = __popcll(K);
                int room = NPOST - kept;
                while (c > room) { K &= ~(1ull << (63 - __clzll(K))); c--; }
                kept += c;
                if (lane == 0) {
                    keptMask[cw] = K;
                    sK = K;
                    sKept = kept;
                    sStop = (kept >= NPOST) ? 1 : 0;
                }
            } else if (tid >= 192 && nbase < end) {
                // prefetch next chunk's diagonal words
                int r = tid - 192;
                sDiag[pb ^ 1][r] = (nbase + r < end) ? __ldg(&g_diag[nbase + r]) : 0ull;
            }
            __syncthreads();

            // incremental suppression: OR kept columns into supB words > cw
            unsigned long long K = sK;
            kept = sKept;
            int wLimit = stage ? WPR : (B1 / 64);   // stage0: tiles exist only for w<64
            if (K && tid < wLimit - (cw + 1)) {
                int w = cw + 1 + tid;
                unsigned long long acc = supB[w];
                unsigned long long km = K;
                while (km) {
                    int jj = __ffsll(km) - 1; km &= km - 1;
                    acc |= __ldg(&g_maskT[(size_t)(base + jj) * WPR + w]);
                }
                supB[w] = acc;
            }
            __syncthreads();
            if (sStop || nbase >= end) break;
        }
    }
    __syncthreads();

    // epilogue: prefix popcounts, then write all kept boxes in parallel
    if (warp == 0) {
        int carry = 0;
        for (int g = 0; g < WPR; g += 32) {
            int w = g + lane;
            int v = (w < WPR) ? __popcll(keptMask[w]) : 0;
            int incl = v;
#pragma unroll
            for (int o = 1; o < 32; o <<= 1) {
                int t2 = __shfl_up_sync(0xffffffffu, incl, o);
                if (lane >= o) incl += t2;
            }
            if (w < WPR) wordBase[w] = carry + incl - v;
            carry += __shfl_sync(0xffffffffu, incl, 31);
        }
    }
    __syncthreads();
    for (int p = tid; p < WPR * 64; p += NTHR) {
        int w = p >> 6, b = p & 63;
        unsigned long long km = keptMask[w];
        if ((km >> b) & 1ull) {
            int pos = wordBase[w] + __popcll(km & ((1ull << b) - 1ull));
            ((float4*)out)[pos] = g_topBox[w * 64 + b];
        }
    }
    if (tid == 0) {
        g_kept = sKept;
        if (stage == 0) g_needMore = (sKept < NPOST && vt > B1) ? 1 : 0;
    }
    for (int w = tid; w < WPR; w += NTHR) { g_keptMaskG[w] = keptMask[w]; g_supBG[w] = supB[w]; }
    __syncthreads();
}

// ------------------------------ mega kernel --------------------------------
__global__ void __launch_bounds__(NTHR) k_mega(
    const float4* __restrict__ anc4, const float4* __restrict__ off4,
    const float* __restrict__ sc,
    const int* __restrict__ ph, const int* __restrict__ pw,
    const int* __restrict__ ps, int n, float* __restrict__ out) {

    int tid = threadIdx.x, bid = blockIdx.x;
    int gid = bid * NTHR + tid;
    int bt = 0;

    // ---- P1: decode + clip + key + hist1 ----
    {
        float H = (float)ph[0];
        float W = (float)pw[0];
        float minsz = __fmul_rn(16.0f, (float)ps[0]);
        for (int i = gid; i < n; i += GSZ) {
            float4 a = anc4[i];
            float4 o = off4[i];
            float ah  = __fsub_rn(a.z, a.x);
            float aw  = __fsub_rn(a.w, a.y);
            float acy = __fadd_rn(a.x, __fmul_rn(0.5f, ah));
            float acx = __fadd_rn(a.y, __fmul_rn(0.5f, aw));
            float cy  = __fadd_rn(__fmul_rn(o.x, ah), acy);
            float cx  = __fadd_rn(__fmul_rn(o.y, aw), acx);
            float h   = __fmul_rn(expf(o.z), ah);
            float w   = __fmul_rn(expf(o.w), aw);
            float y1 = __fsub_rn(cy, __fmul_rn(0.5f, h));
            float x1 = __fsub_rn(cx, __fmul_rn(0.5f, w));
            float y2 = __fadd_rn(cy, __fmul_rn(0.5f, h));
            float x2 = __fadd_rn(cx, __fmul_rn(0.5f, w));
            y1 = fminf(fmaxf(y1, 0.0f), H);
            x1 = fminf(fmaxf(x1, 0.0f), W);
            y2 = fminf(fmaxf(y2, 0.0f), H);
            x2 = fminf(fmaxf(x2, 0.0f), W);
            float rh = __fsub_rn(y2, y1);
            float rw = __fsub_rn(x2, x1);
            bool valid = (rh >= minsz) && (rw >= minsz);
            unsigned key = 0u;
            if (valid) {
                unsigned u = __float_as_uint(sc[i]);
                key = (u & 0x80000000u) ? ~u : (u | 0x80000000u);
                if (key == 0u) key = 1u;
            }
            g_keys[i] = key;
            g_boxes[i] = make_float4(y1, x1, y2, x2);
            if (key) atomicAdd(&g_hist1[key >> 16], 1);
        }
    }
    bt += NBLK; gbar(bt);

    // ---- P2: level-1 threshold search (block0) ----
    if (bid == 0) findPhase(g_hist1, 0, 0);
    bt += NBLK; gbar(bt);

    // ---- P2b (gated, uniform): refinement ----
    if (__ldcg(&g_need2)) {
        unsigned T = __ldcg(&g_T);
        for (int i = gid; i < n; i += GSZ) {
            unsigned key = g_keys[i];
            if (key && (key >> 16) == T) atomicAdd(&g_hist2[key & 0xFFFFu], 1);
        }
        bt += NBLK; gbar(bt);
        if (bid == 0) findPhase(g_hist2, g_C1, 1);
        bt += NBLK; gbar(bt);
    }

    // ---- P3: gather (warp-aggregated) ----
    {
        unsigned kth = __ldcg(&g_kthKey);
        int trips = (n + GSZ - 1) / GSZ;
        for (int t = 0; t < trips; t++) {
            int i = gid + t * GSZ;
            unsigned key = (i < n) ? g_keys[i] : 0u;
            bool want = key && key >= kth;
            unsigned bal = __ballot_sync(0xffffffffu, want);
            if (bal) {
                int lane = tid & 31;
                int leader = __ffs(bal) - 1;
                int basep = 0;
                if (lane == leader) basep = atomicAdd(&g_candCount, __popc(bal));
                basep = __shfl_sync(0xffffffffu, basep, leader);
                if (want) {
                    int p = basep + __popc(bal & ((1u << lane) - 1u));
                    if (p < CAP)
                        g_cand[p] = ((unsigned long long)key << 32) |
                                    (unsigned long long)(0xFFFFFFFFu - (unsigned)i);
                }
            }
        }
    }
    bt += NBLK; gbar(bt);

    // ---- P4: brute-force rank (keys unique); blocks 0..127, j in halves ----
    {
        __shared__ unsigned long long rtile[NTHR];
        if (bid < 128) {
            int m = __ldcg(&g_candCount); if (m > CAP) m = CAP;
            int i = (bid >> 1) * NTHR + tid;
            unsigned long long my = (i < m) ? g_cand[i] : 0ull;
            int j0 = (bid & 1) * (CAP / 2);
            int j1 = j0 + (CAP / 2); if (j1 > m) j1 = m;
            int r = 0;
            for (int jb = j0; jb < j1; jb += NTHR) {
                int j = jb + tid;
                rtile[tid] = (j < j1) ? g_cand[j] : 0ull;
                __syncthreads();
                int lim = j1 - jb; if (lim > NTHR) lim = NTHR;
                if (lim == NTHR) {
#pragma unroll 16
                    for (int k = 0; k < NTHR; k++) r += (rtile[k] > my) ? 1 : 0;
                } else {
                    for (int k = 0; k < lim; k++) r += (rtile[k] > my) ? 1 : 0;
                }
                __syncthreads();
            }
            if (i < m && r) atomicAdd(&g_rank[i], r);
        }
    }
    bt += NBLK; gbar(bt);

    // ---- P5: scatter boxes/areas by rank ----
    {
        int m = __ldcg(&g_candCount); if (m > CAP) m = CAP;
        for (int k = gid; k < m; k += GSZ) {
            int rank = __ldcg(&g_rank[k]);
            if (rank < NPRE) {
                unsigned long long my = g_cand[k];
                unsigned idx = 0xFFFFFFFFu - (unsigned)my;
                float4 b = g_boxes[idx];
                g_topBox[rank] = b;
                g_topArea[rank] = __fmul_rn(__fsub_rn(b.z, b.x), __fsub_rn(b.w, b.y));
            }
        }
        if (gid == 0) g_validTop = (m < NPRE) ? m : NPRE;
    }
    bt += NBLK; gbar(bt);

    // ---- P6: stage-1 mask (tiles rb<64) ----
    maskPhase(0, NTILES1);
    bt += NBLK; gbar(bt);

    // ---- P7: stage-1 resolve (block0) ----
    if (bid == 0) resolvePhase(0, out);
    bt += NBLK; gbar(bt);

    // ---- P8 (gated, uniform): stage-2 ----
    if (__ldcg(&g_needMore)) {
        maskPhase(NTILES1, NTILESA);
        bt += NBLK; gbar(bt);
        if (bid == 0) resolvePhase(1, out);
    }
}

// ------------------------------- launcher ----------------------------------
extern "C" void kernel_launch(void* const* d_in, const int* in_sizes, int n_in,
                              void* d_out, int out_size) {
    const float* anchors = (const float*)d_in[0];
    const float* offsets = (const float*)d_in[1];
    const float* scores  = (const float*)d_in[2];
    const int*   ph      = (const int*)d_in[3];
    const int*   pw      = (const int*)d_in[4];
    const int*   ps      = (const int*)d_in[5];
    float* out = (float*)d_out;

    int n = in_sizes[2];
    if (n > NMAX) n = NMAX;

    k_init<<<NBLK, NTHR>>>(out);
    k_mega<<<NBLK, NTHR>>>((const float4*)anchors, (const float4*)offsets,
                           scores, ph, pw, ps, n, out);
}

// round 11
// speedup vs baseline: 1.0669x; 1.0669x over previous
#include <cuda_runtime.h>
#include <stdint.h>
#include <math.h>

// ---------------------------------------------------------------------------
// ProposalLayer: decode -> clip -> min-size filter -> top-12000 -> NMS(0.7)
//                -> first 2000 kept boxes (zero padded)
// R10: R8 multi-kernel skeleton + exact div-free IoU compare +
//      column-major mask with incremental supB resolve. 9 launches.
// ---------------------------------------------------------------------------

#define NMAX    147456
#define NPRE    12000
#define NPOST   2000
#define CAP     16384
#define WPR     188
#define TOPPAD  12032
#define B1      4096         // stage-1 NMS coverage (64 chunks)
#define JSPLIT  8

// exact midpoint between 0.7f (0x3F333333) and nextafterf up (0x3F333334).
// RN(inter/mu) > 0.7f  <=>  (double)inter >= M2 * (double)mu   (exact, see notes)
#define M2 0.7000000178813934326171875

// ------------------------- scratch (device globals) ------------------------
__device__ unsigned int       g_keys[NMAX];
__device__ float4             g_boxes[NMAX];
__device__ int                g_hist1[65536];
__device__ int                g_hist2[65536];
__device__ unsigned int       g_T;
__device__ int                g_C1;
__device__ int                g_need2;
__device__ unsigned int       g_kthKey;
__device__ int                g_candCount;
__device__ int                g_rankDone;
__device__ unsigned long long g_cand[CAP];
__device__ int                g_rank[CAP];
__device__ float4             g_topBox[TOPPAD];
__device__ float              g_topArea[TOPPAD];
__device__ int                g_validTop;
__device__ unsigned long long g_maskT[(size_t)B1 * 64];   // column-major, stage-1
__device__ unsigned long long g_diag[B1];
__device__ int                g_kept;
__device__ int                g_needMore;
__device__ unsigned long long g_keptMaskG[64];

// ------------------------------- K0: zero ----------------------------------
__global__ void k_zero(float* __restrict__ out) {
    int i = blockIdx.x * blockDim.x + threadIdx.x;
    int stride = gridDim.x * blockDim.x;
    for (int k = i; k < 65536; k += stride) g_hist1[k] = 0;
    for (int k = i; k < NPOST * 4; k += stride) out[k] = 0.0f;
    for (int k = i; k < CAP; k += stride) g_rank[k] = 0;
    if (i == 0) {
        g_candCount = 0;
        g_need2     = 0;
        g_T         = 0;
        g_C1        = 0;
        g_kthKey    = 1u;     // fallback: gather all valid
        g_needMore  = 0;
        g_kept      = 0;
        g_rankDone  = 0;
    }
}

// --------------------- K1: decode + clip + key + hist1 ---------------------
__global__ void k_decode(const float4* __restrict__ anc4,
                         const float4* __restrict__ off4,
                         const float* __restrict__ sc,
                         const int* __restrict__ ph,
                         const int* __restrict__ pw,
                         const int* __restrict__ ps,
                         int n) {
    int i = blockIdx.x * blockDim.x + threadIdx.x;
    if (i >= n) return;

    float H = (float)ph[0];
    float W = (float)pw[0];
    float minsz = __fmul_rn(16.0f, (float)ps[0]);

    float4 a = anc4[i];
    float4 o = off4[i];

    float ah  = __fsub_rn(a.z, a.x);
    float aw  = __fsub_rn(a.w, a.y);
    float acy = __fadd_rn(a.x, __fmul_rn(0.5f, ah));
    float acx = __fadd_rn(a.y, __fmul_rn(0.5f, aw));
    float cy  = __fadd_rn(__fmul_rn(o.x, ah), acy);
    float cx  = __fadd_rn(__fmul_rn(o.y, aw), acx);
    float h   = __fmul_rn(expf(o.z), ah);
    float w   = __fmul_rn(expf(o.w), aw);

    float y1 = __fsub_rn(cy, __fmul_rn(0.5f, h));
    float x1 = __fsub_rn(cx, __fmul_rn(0.5f, w));
    float y2 = __fadd_rn(cy, __fmul_rn(0.5f, h));
    float x2 = __fadd_rn(cx, __fmul_rn(0.5f, w));

    y1 = fminf(fmaxf(y1, 0.0f), H);
    x1 = fminf(fmaxf(x1, 0.0f), W);
    y2 = fminf(fmaxf(y2, 0.0f), H);
    x2 = fminf(fmaxf(x2, 0.0f), W);

    float rh = __fsub_rn(y2, y1);
    float rw = __fsub_rn(x2, x1);
    bool valid = (rh >= minsz) && (rw >= minsz);

    unsigned key = 0u;
    if (valid) {
        unsigned u = __float_as_uint(sc[i]);
        key = (u & 0x80000000u) ? ~u : (u | 0x80000000u);
        if (key == 0u) key = 1u;
    }
    g_keys[i]  = key;
    g_boxes[i] = make_float4(y1, x1, y2, x2);
    if (key) atomicAdd(&g_hist1[key >> 16], 1);
}

// -------- K2: find threshold bucket; set kthKey or request refinement ------
__global__ void k_find1() {
    __shared__ int part[1024];
    int t = threadIdx.x;
    const int4* h4 = (const int4*)g_hist1;
    int s = 0;
#pragma unroll
    for (int k = 0; k < 16; k++) {
        int4 v = h4[t * 16 + k];
        s += v.x + v.y + v.z + v.w;
    }
    part[t] = s;
    __syncthreads();
    for (int offs = 1; offs < 1024; offs <<= 1) {
        int v = part[t] + ((t + offs < 1024) ? part[t + offs] : 0);
        __syncthreads();
        part[t] = v;
        __syncthreads();
    }
    int Sincl = part[t];
    int Sexcl = Sincl - s;
    if (Sexcl < NPRE && Sincl >= NPRE) {
        int base = t * 64;
        int cum = Sexcl;
        for (int b = base + 63; b >= base; b--) {
            int hb = g_hist1[b];
            cum += hb;
            if (cum >= NPRE) {
                g_T  = (unsigned)b;
                g_C1 = cum - hb;
                if (cum <= CAP) {
                    unsigned kk = ((unsigned)b) << 16;
                    g_kthKey = kk ? kk : 1u;
                } else {
                    g_need2 = 1;
                }
                break;
            }
        }
    }
}

// ---- K3 (gated, rare): exact 32-bit kth-key refinement, single block ------
__global__ void __launch_bounds__(1024) k_refine(int n) {
    if (!g_need2) return;
    __shared__ int part[1024];
    __shared__ int sTc, sBase;
    int t = threadIdx.x;
    // zero hist2
    for (int k = t; k < 65536; k += 1024) g_hist2[k] = 0;
    __syncthreads();
    unsigned T = g_T;
    for (int i = t; i < n; i += 1024) {
        unsigned key = g_keys[i];
        if (key && (key >> 16) == T) atomicAdd(&g_hist2[key & 0xFFFFu], 1);
    }
    __syncthreads();
    int C1 = g_C1;
    int s = 0;
    for (int k = 0; k < 64; k++) s += __ldcg(&g_hist2[t * 64 + k]);
    part[t] = s;
    __syncthreads();
    for (int offs = 1; offs < 1024; offs <<= 1) {
        int v = part[t] + ((t + offs < 1024) ? part[t + offs] : 0);
        __syncthreads();
        part[t] = v;
        __syncthreads();
    }
    int Sincl = part[t];
    int Sexcl = Sincl - s;
    if (C1 + Sexcl < NPRE && C1 + Sincl >= NPRE) {
        int base = t * 64;
        int cum = C1 + Sexcl;
        for (int b = base + 63; b >= base; b--) {
            cum += __ldcg(&g_hist2[b]);
            if (cum >= NPRE) {
                g_kthKey = (T << 16) | (unsigned)b;
                break;
            }
        }
    }
}

// ---------------- K4: gather (warp-aggregated atomics) ---------------------
__global__ void k_gather(int n) {
    int i = blockIdx.x * blockDim.x + threadIdx.x;
    unsigned key = (i < n) ? g_keys[i] : 0u;
    unsigned kth = g_kthKey;
    bool want = key && key >= kth;
    unsigned bal = __ballot_sync(0xffffffffu, want);
    if (!bal) return;
    int lane = threadIdx.x & 31;
    int leader = __ffs(bal) - 1;
    int base = 0;
    if (lane == leader) base = atomicAdd(&g_candCount, __popc(bal));
    base = __shfl_sync(0xffffffffu, base, leader);
    if (want) {
        int p = base + __popc(bal & ((1u << lane) - 1u));
        if (p < CAP) {
            // composite: score key desc, then index asc (top_k tie-break)
            g_cand[p] = ((unsigned long long)key << 32) |
                        (unsigned long long)(0xFFFFFFFFu - (unsigned)i);
        }
    }
}

// ------ K5: partial rank (j split 8 ways) + last-block scatter -------------
__global__ void __launch_bounds__(256) k_rankscatter() {
    __shared__ unsigned long long tile[256];
    __shared__ int sLastBlk;
    int m = g_candCount; if (m > CAP) m = CAP;
    int j0 = blockIdx.y * (CAP / JSPLIT);
    int i = blockIdx.x * 256 + threadIdx.x;

    if (j0 < m) {
        int j1 = j0 + (CAP / JSPLIT); if (j1 > m) j1 = m;
        unsigned long long my = (i < m) ? g_cand[i] : 0ull;
        int r = 0;
        for (int jb = j0; jb < j1; jb += 256) {
            int j = jb + threadIdx.x;
            tile[threadIdx.x] = (j < j1) ? g_cand[j] : 0ull;
            __syncthreads();
            int lim = j1 - jb;
            if (lim >= 256) {
#pragma unroll 16
                for (int k = 0; k < 256; k++) r += (tile[k] > my) ? 1 : 0;
            } else {
                for (int k = 0; k < lim; k++) r += (tile[k] > my) ? 1 : 0;
            }
            __syncthreads();
        }
        if (i < m && r) atomicAdd(&g_rank[i], r);
    }

    __threadfence();
    __syncthreads();
    if (threadIdx.x == 0)
        sLastBlk = (atomicAdd(&g_rankDone, 1) == (int)(gridDim.x * gridDim.y) - 1);
    __syncthreads();
    if (!sLastBlk) return;

    for (int k = threadIdx.x; k < m; k += 256) {
        int rank = __ldcg(&g_rank[k]);
        if (rank < NPRE) {
            unsigned long long my = g_cand[k];
            unsigned idx = 0xFFFFFFFFu - (unsigned)my;
            float4 b = g_boxes[idx];
            g_topBox[rank]  = b;
            g_topArea[rank] = __fmul_rn(__fsub_rn(b.z, b.x), __fsub_rn(b.w, b.y));
        }
    }
    if (threadIdx.x == 0) g_validTop = (m < NPRE) ? m : NPRE;
}

// --------------- IoU decision (exact, div-free; see M2 note) ---------------
__device__ __forceinline__ bool iou_gt(float4 a, float aa, float4 b, float ab) {
    float ty = fmaxf(a.x, b.x);
    float tx = fmaxf(a.y, b.y);
    float by = fminf(a.z, b.z);
    float bx = fminf(a.w, b.w);
    float hh = fmaxf(__fsub_rn(by, ty), 0.0f);
    float ww = fmaxf(__fsub_rn(bx, tx), 0.0f);
    float inter = __fmul_rn(hh, ww);
    float uni = __fsub_rn(__fadd_rn(aa, ab), inter);
    float mu  = fmaxf(uni, 1e-9f);
    return (double)inter >= M2 * (double)mu;
}

// ---- K6: stage-1 suppression mask, COLUMN-major words + diag row words ----
// block (cb, rb), 64 threads; thread t = column j within cb.
__global__ void k_maskT() {
    int cb = blockIdx.x;
    int rb = blockIdx.y;
    if (cb > rb) return;

    __shared__ float4 rB[64];
    __shared__ float  rA[64];
    int t = threadIdx.x;
    rB[t] = g_topBox[rb * 64 + t];
    rA[t] = g_topArea[rb * 64 + t];
    __syncthreads();

    bool isDiag = (rb == cb);
    int colg = cb * 64 + t;
    float4 cbox = isDiag ? rB[t] : g_topBox[colg];
    float  ca   = isDiag ? rA[t] : g_topArea[colg];

    // column word: bit r set iff column j suppresses row r (j < r)
    unsigned long long word = 0ull;
    int r0 = isDiag ? t + 1 : 0;
    for (int r = r0; r < 64; r++)
        if (iou_gt(cbox, ca, rB[r], rA[r])) word |= (1ull << r);
    g_maskT[(size_t)colg * 64 + rb] = word;

    if (isDiag) {
        // row word: row t vs columns j < t (same chunk)
        unsigned long long dw = 0ull;
        float4 rbox = rB[t];
        float  ra = rA[t];
        for (int j = 0; j < t; j++)
            if (iou_gt(rbox, ra, rB[j], rA[j])) dw |= (1ull << j);
        g_diag[rb * 64 + t] = dw;
    }
}

// ------ K7: resolve with incremental suppression bitmap (stage 1) ----------
__global__ void __launch_bounds__(256, 1) k_resolve(float* __restrict__ out) {
    __shared__ unsigned long long supB[64];
    __shared__ unsigned long long keptMask[64];
    __shared__ unsigned long long sDiag[2][64];
    __shared__ unsigned long long sK;
    __shared__ int sKept, sStop;
    __shared__ int wordBase[64];

    int tid = threadIdx.x, lane = tid & 31, warp = tid >> 5;
    int vt = g_validTop;
    int end = (vt < B1) ? vt : B1;

    if (tid < 64) { supB[tid] = 0ull; keptMask[tid] = 0ull; }
    if (tid == 0) { sKept = 0; sStop = (end <= 0) ? 1 : 0; }
    if (tid < 64) sDiag[0][tid] = (tid < end) ? __ldg(&g_diag[tid]) : 0ull;
    __syncthreads();

    if (!sStop) {
        int kept = 0;
        int pb = 0;
        for (int base = 0; ; base += 64, pb ^= 1) {
            int cw = base >> 6;
            int cn = end - base; if (cn > 64) cn = 64;
            int nbase = base + 64;

            if (warp == 0) {
                // exact greedy within chunk: frontier rounds == sequential greedy
                unsigned long long sup = supB[cw];
                unsigned long long cand = ~sup;
                if (cn < 64) cand &= (1ull << cn) - 1ull;
                unsigned long long rowLo = sDiag[pb][lane];
                unsigned long long rowHi = sDiag[pb][lane + 32];
                unsigned long long U = cand, K = 0ull;
                while (U) {
                    bool flo = ((U >> lane) & 1ull) && ((rowLo & U) == 0ull);
                    bool fhi = ((U >> (lane + 32)) & 1ull) && ((rowHi & U) == 0ull);
                    unsigned long long F =
                          (unsigned long long)__ballot_sync(0xffffffffu, flo)
                        | ((unsigned long long)__ballot_sync(0xffffffffu, fhi) << 32);
                    K |= F;
                    bool qlo = (rowLo & F) != 0ull;
                    bool qhi = (rowHi & F) != 0ull;
                    unsigned long long S =
                          (unsigned long long)__ballot_sync(0xffffffffu, qlo)
                        | ((unsigned long long)__ballot_sync(0xffffffffu, qhi) << 32);
                    U &= ~(F | S | K);
                }
                int c = __popcll(K);
                int room = NPOST - kept;
                while (c > room) { K &= ~(1ull << (63 - __clzll(K))); c--; }
                kept += c;
                if (lane == 0) {
                    keptMask[cw] = K;
                    sK = K;
                    sKept = kept;
                    sStop = (kept >= NPOST) ? 1 : 0;
                }
            } else if (tid >= 192 && nbase < end) {
                int r = tid - 192;
                sDiag[pb ^ 1][r] = (nbase + r < end) ? __ldg(&g_diag[nbase + r]) : 0ull;
            }
            __syncthreads();

            // incremental suppression: OR kept columns into supB words > cw
            unsigned long long K = sK;
            kept = sKept;
            if (K && tid < 64 - (cw + 1)) {
                int w = cw + 1 + tid;
                unsigned long long acc = supB[w];
                unsigned long long km = K;
                while (km) {
                    int jj = __ffsll(km) - 1; km &= km - 1;
                    acc |= __ldg(&g_maskT[(size_t)(base + jj) * 64 + w]);
                }
                supB[w] = acc;
            }
            __syncthreads();
            if (sStop || nbase >= end) break;
        }
    }
    __syncthreads();

    // epilogue: prefix popcounts + parallel output writes
    if (warp == 0) {
        int w = lane;              // 64 words in 2 groups
        int carry = 0;
        for (int g = 0; g < 64; g += 32) {
            int ww = g + lane;
            int v = __popcll(keptMask[ww]);
            int incl = v;
#pragma unroll
            for (int o = 1; o < 32; o <<= 1) {
                int t2 = __shfl_up_sync(0xffffffffu, incl, o);
                if (lane >= o) incl += t2;
            }
            wordBase[ww] = carry + incl - v;
            carry += __shfl_sync(0xffffffffu, incl, 31);
        }
        (void)w;
    }
    __syncthreads();
    for (int p = tid; p < 64 * 64; p += 256) {
        int w = p >> 6, b = p & 63;
        unsigned long long km = keptMask[w];
        if ((km >> b) & 1ull) {
            int pos = wordBase[w] + __popcll(km & ((1ull << b) - 1ull));
            ((float4*)out)[pos] = g_topBox[w * 64 + b];
        }
    }
    if (tid == 0) {
        g_kept = sKept;
        g_needMore = (sKept < NPOST && vt > B1) ? 1 : 0;
    }
    if (tid < 64) g_keptMaskG[tid] = keptMask[tid];
}

// ---- K8 (gated, rare): direct greedy continuation for ranks >= B1 ---------
__global__ void __launch_bounds__(1024, 1) k_tail(float* __restrict__ out) {
    if (!g_needMore) return;

    __shared__ float4 kb[NPOST];
    __shared__ float  ka[NPOST];
    __shared__ float4 cb[64];
    __shared__ float  ca[64];
    __shared__ unsigned long long lmask[64];
    __shared__ int    supf[64];
    __shared__ unsigned long long sKeepLocal;
    __shared__ int    sKept;
    __shared__ int    wordBase[64];

    int tid = threadIdx.x, lane = tid & 31, wid = tid >> 5;
    int vt = g_validTop;
    int kept0 = g_kept;

    // rebuild kept list (in order) from stage-1 keptMask
    if (wid == 0) {
        int carry = 0;
        for (int g = 0; g < 64; g += 32) {
            int ww = g + lane;
            int v = __popcll(__ldg(&g_keptMaskG[ww]));
            int incl = v;
#pragma unroll
            for (int o = 1; o < 32; o <<= 1) {
                int t2 = __shfl_up_sync(0xffffffffu, incl, o);
                if (lane >= o) incl += t2;
            }
            wordBase[ww] = carry + incl - v;
            carry += __shfl_sync(0xffffffffu, incl, 31);
        }
    }
    __syncthreads();
    for (int p = tid; p < 64 * 64; p += 1024) {
        int w = p >> 6, b = p & 63;
        unsigned long long km = __ldg(&g_keptMaskG[w]);
        if ((km >> b) & 1ull) {
            int pos = wordBase[w] + __popcll(km & ((1ull << b) - 1ull));
            kb[pos] = g_topBox[w * 64 + b];
            ka[pos] = g_topArea[w * 64 + b];
        }
    }
    __syncthreads();

    int kept = kept0;
    for (int base = B1; base < vt && kept < NPOST; base += 64) {
        int cn = vt - base; if (cn > 64) cn = 64;

        if (tid < 64) {
            supf[tid]  = 0;
            lmask[tid] = 0ull;
            if (tid < cn) {
                cb[tid] = g_topBox[base + tid];
                ca[tid] = g_topArea[base + tid];
            }
        }
        __syncthreads();

        for (int i = wid; i < cn; i += 32) {
            float4 bi = cb[i];
            float  ai = ca[i];
            bool any = false;
            for (int j = lane; j < kept; j += 32)
                if (iou_gt(bi, ai, kb[j], ka[j])) { any = true; break; }
            bool w = __any_sync(0xffffffffu, any);
            if (w && lane == 0) supf[i] = 1;
        }
        for (int p = tid; p < 64 * 64; p += 1024) {
            int i = p >> 6, j = p & 63;
            if (i < cn && j < i)
                if (iou_gt(cb[i], ca[i], cb[j], ca[j]))
                    atomicOr(&lmask[i], 1ull << j);
        }
        __syncthreads();

        if (tid == 0) {
            unsigned long long kl = 0ull;
            int kc = kept;
            for (int i = 0; i < cn && kc < NPOST; i++) {
                if (!supf[i] && !(lmask[i] & kl)) { kl |= 1ull << i; kc++; }
            }
            sKeepLocal = kl; sKept = kc;
        }
        __syncthreads();

        unsigned long long kl = sKeepLocal;
        if (tid < cn && ((kl >> tid) & 1ull)) {
            int pos = kept + __popcll(kl & ((1ull << tid) - 1ull));
            kb[pos] = cb[tid];
            ka[pos] = ca[tid];
            ((float4*)out)[pos] = cb[tid];
        }
        __syncthreads();
        kept = sKept;
        __syncthreads();
    }
}

// ------------------------------- launcher ----------------------------------
extern "C" void kernel_launch(void* const* d_in, const int* in_sizes, int n_in,
                              void* d_out, int out_size) {
    const float* anchors = (const float*)d_in[0];
    const float* offsets = (const float*)d_in[1];
    const float* scores  = (const float*)d_in[2];
    const int*   ph      = (const int*)d_in[3];
    const int*   pw      = (const int*)d_in[4];
    const int*   ps      = (const int*)d_in[5];
    float* out = (float*)d_out;

    int n = in_sizes[2];
    if (n > NMAX) n = NMAX;
    int nb = (n + 255) / 256;

    k_zero<<<128, 256>>>(out);
    k_decode<<<nb, 256>>>((const float4*)anchors, (const float4*)offsets,
                          scores, ph, pw, ps, n);
    k_find1<<<1, 1024>>>();
    k_refine<<<1, 1024>>>(n);               // gated on g_need2 (rare)
    k_gather<<<nb, 256>>>(n);
    k_rankscatter<<<dim3(64, JSPLIT), 256>>>();
    k_maskT<<<dim3(64, 64), 64>>>();
    k_resolve<<<1, 256>>>(out);
    k_tail<<<1, 1024>>>(out);               // gated on g_needMore (rare)
}